// round 3
// baseline (speedup 1.0000x reference)
#include <cuda_runtime.h>
#include <cuda_bf16.h>

#define B_ 128
#define T_ 512
#define D_ 256
#define E_ 512
#define H_ 512

// ---------------- scratch (static device globals; no allocation) ----------------
__device__ float g_wcomb[4 * H_ * D_];            // [2048][256], row = gate*512 + h  (gate order i,f,g,o)
__device__ float g_bcomb[4 * H_];                 // [2048]
__device__ float g_xs[134217728];                 // [t][gate][b][h] = 512*4*128*512 (512 MB)
__device__ float g_hbuf[2][B_ * H_];              // double-buffered hidden state
__device__ unsigned int g_cnt;                    // grid barrier counter

__global__ void reset_kernel() { g_cnt = 0u; }

// ---------------- Wcomb = Wgate(2048x512) @ We(512x256) ----------------
__global__ void wcomb_kernel(const float* __restrict__ Wi, const float* __restrict__ Wf,
                             const float* __restrict__ Wg, const float* __restrict__ Wo,
                             const float* __restrict__ We) {
    __shared__ float As[16][65];   // [k][m]
    __shared__ float Bs[16][65];   // [k][n]
    const int bm = blockIdx.y * 64;   // over 2048 rows
    const int bn = blockIdx.x * 64;   // over 256 cols
    const int tid = threadIdx.x;
    float acc[4][4] = {};
    const int tx = tid % 16, ty = tid / 16;

    for (int k0 = 0; k0 < 512; k0 += 16) {
        for (int i = tid; i < 64 * 16; i += 256) {
            int r = i / 16, kk = i % 16;
            int row = bm + r;
            int gate = row >> 9, h = row & 511;
            const float* W = (gate == 0) ? Wi : (gate == 1) ? Wf : (gate == 2) ? Wg : Wo;
            As[kk][r] = W[h * 512 + k0 + kk];
        }
        for (int i = tid; i < 64 * 16; i += 256) {
            int kk = i / 64, c = i % 64;
            Bs[kk][c] = We[(k0 + kk) * 256 + bn + c];
        }
        __syncthreads();
#pragma unroll
        for (int kk = 0; kk < 16; kk++) {
            float a[4], b[4];
#pragma unroll
            for (int i = 0; i < 4; i++) a[i] = As[kk][ty * 4 + i];
#pragma unroll
            for (int j = 0; j < 4; j++) b[j] = Bs[kk][tx * 4 + j];
#pragma unroll
            for (int i = 0; i < 4; i++)
#pragma unroll
                for (int j = 0; j < 4; j++) acc[i][j] += a[i] * b[j];
        }
        __syncthreads();
    }
#pragma unroll
    for (int i = 0; i < 4; i++)
#pragma unroll
        for (int j = 0; j < 4; j++)
            g_wcomb[(bm + ty * 4 + i) * 256 + bn + tx * 4 + j] = acc[i][j];
}

// ---------------- bcomb = Wgate @ be + bgate ----------------
__global__ void bcomb_kernel(const float* __restrict__ Wi, const float* __restrict__ Wf,
                             const float* __restrict__ Wg, const float* __restrict__ Wo,
                             const float* __restrict__ be,
                             const float* __restrict__ bi, const float* __restrict__ bf,
                             const float* __restrict__ bg, const float* __restrict__ bo) {
    int r = blockIdx.x * 256 + threadIdx.x;   // 2048 total
    if (r >= 2048) return;
    int gate = r >> 9, h = r & 511;
    const float* W = (gate == 0) ? Wi : (gate == 1) ? Wf : (gate == 2) ? Wg : Wo;
    const float* bb = (gate == 0) ? bi : (gate == 1) ? bf : (gate == 2) ? bg : bo;
    float s = 0.f;
    for (int e = 0; e < 512; e++) s += W[h * 512 + e] * be[e];
    g_bcomb[r] = s + bb[h];
}

// ---------------- xs = x(65536x256) @ Wcomb^T(256x2048) + bcomb, scattered to [t][g][b][h] ----------------
__global__ void xs_gemm_kernel(const float* __restrict__ x) {
    __shared__ __align__(16) float As[16][132];   // [k][m]
    __shared__ __align__(16) float Bs[16][132];   // [k][n]
    const int bm = blockIdx.x * 128;   // M = 65536, grid.x = 512
    const int bn = blockIdx.y * 128;   // N = 2048,  grid.y = 16
    const int tid = threadIdx.x;
    const int tx = tid % 16, ty = tid / 16;
    float acc[8][8] = {};

    for (int k0 = 0; k0 < 256; k0 += 16) {
        for (int i = tid; i < 512; i += 256) {
            int r = i >> 2, f = i & 3;
            float4 v = *(const float4*)&x[(size_t)(bm + r) * 256 + k0 + f * 4];
            As[f * 4 + 0][r] = v.x; As[f * 4 + 1][r] = v.y;
            As[f * 4 + 2][r] = v.z; As[f * 4 + 3][r] = v.w;
        }
        for (int i = tid; i < 512; i += 256) {
            int c = i >> 2, f = i & 3;
            float4 v = *(const float4*)&g_wcomb[(size_t)(bn + c) * 256 + k0 + f * 4];
            Bs[f * 4 + 0][c] = v.x; Bs[f * 4 + 1][c] = v.y;
            Bs[f * 4 + 2][c] = v.z; Bs[f * 4 + 3][c] = v.w;
        }
        __syncthreads();
#pragma unroll
        for (int kk = 0; kk < 16; kk++) {
            float a[8], b[8];
            *(float4*)&a[0] = *(const float4*)&As[kk][ty * 8];
            *(float4*)&a[4] = *(const float4*)&As[kk][ty * 8 + 4];
            *(float4*)&b[0] = *(const float4*)&Bs[kk][tx * 8];
            *(float4*)&b[4] = *(const float4*)&Bs[kk][tx * 8 + 4];
#pragma unroll
            for (int i = 0; i < 8; i++)
#pragma unroll
                for (int j = 0; j < 8; j++) acc[i][j] += a[i] * b[j];
        }
        __syncthreads();
    }

    float bias[8];
#pragma unroll
    for (int j = 0; j < 8; j++) bias[j] = g_bcomb[bn + tx * 8 + j];

#pragma unroll
    for (int i = 0; i < 8; i++) {
        int m = bm + ty * 8 + i;
        int t = m & 511, bidx = m >> 9;
#pragma unroll
        for (int jj = 0; jj < 2; jj++) {
            int n = bn + tx * 8 + jj * 4;
            int gate = n >> 9, h = n & 511;
            float4 v;
            v.x = acc[i][jj * 4 + 0] + bias[jj * 4 + 0];
            v.y = acc[i][jj * 4 + 1] + bias[jj * 4 + 1];
            v.z = acc[i][jj * 4 + 2] + bias[jj * 4 + 2];
            v.w = acc[i][jj * 4 + 3] + bias[jj * 4 + 3];
            *(float4*)&g_xs[(size_t)((t * 4 + gate) * 128 + bidx) * 512 + h] = v;
        }
    }
}

// ---------------- persistent recurrent scan ----------------
// 128 blocks x 256 threads. Block = (b_chunk in [0,4), h_chunk in [0,32)):
//   32 batches x 16 h-cols x 4 gates = 2048 dot products of length 512 per step.
__global__ void __launch_bounds__(256, 1) scan_kernel(
        const float* __restrict__ h0, const float* __restrict__ c0,
        const float* __restrict__ Ri, const float* __restrict__ Rf,
        const float* __restrict__ Rg, const float* __restrict__ Ro,
        float* __restrict__ out) {
    __shared__ float hs[32][65];      // [b_local][k]
    __shared__ float rs[64][65];      // [col][k], col = gate*16 + h_local
    __shared__ float acc_s[64][33];   // [col][b_local]

    const int tid = threadIdx.x;
    const int bchunk = blockIdx.x >> 5;      // 0..3
    const int hchunk = blockIdx.x & 31;      // 0..31
    const int b0 = bchunk * 32;
    const int hb = hchunk * 16;
    const int bg = tid >> 4;                 // 0..15 -> rows 2bg,2bg+1
    const int cg = tid & 15;                 // 0..15 -> cols 4cg..4cg+3

    // c state in registers: 2 (b,h) pairs per thread
    float creg[2], hlast[2];
#pragma unroll
    for (int q = 0; q < 2; q++) {
        int p = tid * 2 + q;
        int bl = p >> 4, hl = p & 15;
        creg[q] = c0[(b0 + bl) * 512 + hb + hl];
        hlast[q] = 0.f;
    }

    for (int t = 0; t < 512; t++) {
        const float* hprev = (t == 0) ? h0 : g_hbuf[t & 1];
        float acc[2][4] = {};

        for (int k0 = 0; k0 < 512; k0 += 64) {
            // load h tile (cross-SM data -> L2 loads)
#pragma unroll
            for (int ii = 0; ii < 2; ii++) {
                int i = tid + ii * 256;
                int r = i >> 4, f = i & 15;
                float4 v = __ldcg((const float4*)&hprev[(b0 + r) * 512 + k0 + f * 4]);
                hs[r][f * 4 + 0] = v.x; hs[r][f * 4 + 1] = v.y;
                hs[r][f * 4 + 2] = v.z; hs[r][f * 4 + 3] = v.w;
            }
            // load R tile (constant across steps -> L1 resident)
#pragma unroll
            for (int ii = 0; ii < 4; ii++) {
                int i = tid + ii * 256;
                int c = i >> 4, f = i & 15;
                int gate = c >> 4;
                const float* R = (gate == 0) ? Ri : (gate == 1) ? Rf : (gate == 2) ? Rg : Ro;
                float4 v = *(const float4*)&R[(hb + (c & 15)) * 512 + k0 + f * 4];
                rs[c][f * 4 + 0] = v.x; rs[c][f * 4 + 1] = v.y;
                rs[c][f * 4 + 2] = v.z; rs[c][f * 4 + 3] = v.w;
            }
            __syncthreads();
#pragma unroll 16
            for (int kk = 0; kk < 64; kk++) {
                float a0 = hs[2 * bg + 0][kk];
                float a1 = hs[2 * bg + 1][kk];
                float r0 = rs[4 * cg + 0][kk];
                float r1 = rs[4 * cg + 1][kk];
                float r2 = rs[4 * cg + 2][kk];
                float r3 = rs[4 * cg + 3][kk];
                acc[0][0] += a0 * r0; acc[0][1] += a0 * r1;
                acc[0][2] += a0 * r2; acc[0][3] += a0 * r3;
                acc[1][0] += a1 * r0; acc[1][1] += a1 * r1;
                acc[1][2] += a1 * r2; acc[1][3] += a1 * r3;
            }
            __syncthreads();
        }

#pragma unroll
        for (int i = 0; i < 2; i++)
#pragma unroll
            for (int j = 0; j < 4; j++)
                acc_s[4 * cg + j][2 * bg + i] = acc[i][j];
        __syncthreads();

        // pointwise: gates + state update
        const float* xsbase = &g_xs[(size_t)t * 4 * B_ * H_];
        float* hnext = g_hbuf[(t + 1) & 1];
#pragma unroll
        for (int q = 0; q < 2; q++) {
            int p = tid * 2 + q;
            int bl = p >> 4, hl = p & 15;
            int bgl = b0 + bl, hgl = hb + hl;
            float ipre = acc_s[0 + hl][bl]  + xsbase[(size_t)(0 * 128 + bgl) * 512 + hgl];
            float fpre = acc_s[16 + hl][bl] + xsbase[(size_t)(1 * 128 + bgl) * 512 + hgl];
            float gpre = acc_s[32 + hl][bl] + xsbase[(size_t)(2 * 128 + bgl) * 512 + hgl];
            float opre = acc_s[48 + hl][bl] + xsbase[(size_t)(3 * 128 + bgl) * 512 + hgl];
            float ig = 1.f / (1.f + expf(-ipre));
            float fg = 1.f / (1.f + expf(-fpre));
            float gv = tanhf(gpre);
            float og = 1.f / (1.f + expf(-opre));
            float cn = gv * ig + fg * creg[q];
            creg[q] = cn;
            float hn = og * tanhf(cn);
            hlast[q] = hn;
            hnext[bgl * 512 + hgl] = hn;
            out[((size_t)bgl * 512 + t) * 512 + hgl] = hn;
        }

        // grid barrier
        __threadfence();
        __syncthreads();
        if (tid == 0) {
            atomicAdd(&g_cnt, 1u);
            unsigned target = (unsigned)(t + 1) * 128u;
            while (*(volatile unsigned int*)&g_cnt < target) { __nanosleep(64); }
        }
        __syncthreads();
    }

    // epilogue: h_last at 33554432, c_last at 33620 -- 33554432 + 65536
#pragma unroll
    for (int q = 0; q < 2; q++) {
        int p = tid * 2 + q;
        int bl = p >> 4, hl = p & 15;
        size_t idx = (size_t)(b0 + bl) * 512 + hb + hl;
        out[(size_t)33554432 + idx] = hlast[q];
        out[(size_t)33620224 - 256 + idx] = creg[q];   // 33554432 + 65536 = 33619968
    }
}

extern "C" void kernel_launch(void* const* d_in, const int* in_sizes, int n_in,
                              void* d_out, int out_size) {
    const float* x  = (const float*)d_in[0];
    const float* h0 = (const float*)d_in[1];
    const float* c0 = (const float*)d_in[2];
    const float* We = (const float*)d_in[3];
    const float* be = (const float*)d_in[4];
    const float* Wf = (const float*)d_in[5];
    const float* bf = (const float*)d_in[6];
    const float* Wi = (const float*)d_in[7];
    const float* bi = (const float*)d_in[8];
    const float* Wg = (const float*)d_in[9];
    const float* bg = (const float*)d_in[10];
    const float* Wo = (const float*)d_in[11];
    const float* bo = (const float*)d_in[12];
    const float* Rf = (const float*)d_in[13];
    const float* Ri = (const float*)d_in[14];
    const float* Rg = (const float*)d_in[15];
    const float* Ro = (const float*)d_in[16];
    float* out = (float*)d_out;

    reset_kernel<<<1, 1>>>();
    wcomb_kernel<<<dim3(4, 32), 256>>>(Wi, Wf, Wg, Wo, We);
    bcomb_kernel<<<8, 256>>>(Wi, Wf, Wg, Wo, be, bi, bf, bg, bo);
    xs_gemm_kernel<<<dim3(512, 16), 256>>>(x);
    scan_kernel<<<128, 256>>>(h0, c0, Ri, Rf, Rg, Ro, out);
}

// round 5
// speedup vs baseline: 3.5332x; 3.5332x over previous
#include <cuda_runtime.h>
#include <cuda_fp16.h>
#include <cstdint>

// B=128, T=512, DIM=256, E=512, H=512
// out = hidden_seq(33554432) + h_last at 33554432 + c_last at 33619968

__device__ __align__(16) float g_wcomb[2048 * 256];
__device__ __align__(16) float g_bcomb[2048];
__device__ __align__(16) float g_xs[134217728];      // [t][gate][b][h] fp32
__device__ __align__(16) __half g_xh[16777216];      // X hi [65536][256]
__device__ __align__(16) __half g_xl[16777216];      // X lo
__device__ __align__(16) __half g_wch[524288];       // Wcomb hi [2048][256]
__device__ __align__(16) __half g_wcl[524288];       // Wcomb lo
__device__ __align__(16) __half g_rph[1048576];      // R packed hi [2048][512]; row=hc*64+gate*16+j <-> Rgate[hc*16+j]
__device__ __align__(16) __half g_rpl[1048576];      // R packed lo
__device__ __align__(16) __half g_hh[2][65536];      // h hi double buffer [b][k]
__device__ __align__(16) __half g_hl[2][65536];      // h lo
__device__ unsigned g_cnt;

// ---------- helpers ----------
__device__ __forceinline__ uint32_t smem_u32(const void* p) {
    uint32_t a;
    asm("{ .reg .u64 t; cvta.to.shared.u64 t, %1; cvt.u32.u64 %0, t; }" : "=r"(a) : "l"(p));
    return a;
}
__device__ __forceinline__ void ldm_x4(uint32_t* a, uint32_t addr) {
    asm volatile("ldmatrix.sync.aligned.m8n8.x4.shared.b16 {%0,%1,%2,%3}, [%4];"
                 : "=r"(a[0]), "=r"(a[1]), "=r"(a[2]), "=r"(a[3]) : "r"(addr));
}
__device__ __forceinline__ void ldm_x2(uint32_t& b0, uint32_t& b1, uint32_t addr) {
    asm volatile("ldmatrix.sync.aligned.m8n8.x2.shared.b16 {%0,%1}, [%2];"
                 : "=r"(b0), "=r"(b1) : "r"(addr));
}
__device__ __forceinline__ void mma16816(float* d, const uint32_t* a, uint32_t b0, uint32_t b1) {
    asm volatile("mma.sync.aligned.m16n8k16.row.col.f32.f16.f16.f32 "
                 "{%0,%1,%2,%3},{%4,%5,%6,%7},{%8,%9},{%0,%1,%2,%3};"
                 : "+f"(d[0]), "+f"(d[1]), "+f"(d[2]), "+f"(d[3])
                 : "r"(a[0]), "r"(a[1]), "r"(a[2]), "r"(a[3]), "r"(b0), "r"(b1));
}
__device__ __forceinline__ void cpa16(uint32_t saddr, const void* g) {
    asm volatile("cp.async.cg.shared.global [%0], [%1], 16;" :: "r"(saddr), "l"(g));
}
#define CP_COMMIT() asm volatile("cp.async.commit_group;" ::: "memory")
#define CP_WAIT(N)  asm volatile("cp.async.wait_group %0;" :: "n"(N) : "memory")

__device__ __forceinline__ void split1(float v, __half& h, __half& l) {
    h = __float2half_rn(v);
    l = __float2half_rn(v - __half2float(h));
}
__device__ __forceinline__ void store_split4(__half* dh, __half* dl, float4 v) {
    __half h0, h1, h2, h3, l0, l1, l2, l3;
    split1(v.x, h0, l0); split1(v.y, h1, l1); split1(v.z, h2, l2); split1(v.w, h3, l3);
    ((__half2*)dh)[0] = __halves2half2(h0, h1);
    ((__half2*)dh)[1] = __halves2half2(h2, h3);
    ((__half2*)dl)[0] = __halves2half2(l0, l1);
    ((__half2*)dl)[1] = __halves2half2(l2, l3);
}

// ---------- prep kernels ----------
__global__ void reset_kernel() { g_cnt = 0u; }

__global__ void wcomb_kernel(const float* __restrict__ Wi, const float* __restrict__ Wf,
                             const float* __restrict__ Wg, const float* __restrict__ Wo,
                             const float* __restrict__ We) {
    __shared__ float As[16][65];
    __shared__ float Bs[16][65];
    const int bm = blockIdx.y * 64, bn = blockIdx.x * 64, tid = threadIdx.x;
    const int tx = tid % 16, ty = tid / 16;
    float acc[4][4] = {};
    for (int k0 = 0; k0 < 512; k0 += 16) {
        for (int i = tid; i < 1024; i += 256) {
            int r = i / 16, kk = i % 16, row = bm + r, gate = row >> 9, h = row & 511;
            const float* W = (gate == 0) ? Wi : (gate == 1) ? Wf : (gate == 2) ? Wg : Wo;
            As[kk][r] = W[h * 512 + k0 + kk];
        }
        for (int i = tid; i < 1024; i += 256) {
            int kk = i / 64, c = i % 64;
            Bs[kk][c] = We[(k0 + kk) * 256 + bn + c];
        }
        __syncthreads();
#pragma unroll
        for (int kk = 0; kk < 16; kk++) {
            float a[4], b[4];
#pragma unroll
            for (int i = 0; i < 4; i++) a[i] = As[kk][ty * 4 + i];
#pragma unroll
            for (int j = 0; j < 4; j++) b[j] = Bs[kk][tx * 4 + j];
#pragma unroll
            for (int i = 0; i < 4; i++)
#pragma unroll
                for (int j = 0; j < 4; j++) acc[i][j] += a[i] * b[j];
        }
        __syncthreads();
    }
#pragma unroll
    for (int i = 0; i < 4; i++)
#pragma unroll
        for (int j = 0; j < 4; j++)
            g_wcomb[(bm + ty * 4 + i) * 256 + bn + tx * 4 + j] = acc[i][j];
}

__global__ void bcomb_kernel(const float* __restrict__ Wi, const float* __restrict__ Wf,
                             const float* __restrict__ Wg, const float* __restrict__ Wo,
                             const float* __restrict__ be,
                             const float* __restrict__ bi, const float* __restrict__ bf,
                             const float* __restrict__ bg, const float* __restrict__ bo) {
    int r = blockIdx.x * 256 + threadIdx.x;
    if (r >= 2048) return;
    int gate = r >> 9, h = r & 511;
    const float* W = (gate == 0) ? Wi : (gate == 1) ? Wf : (gate == 2) ? Wg : Wo;
    const float* bb = (gate == 0) ? bi : (gate == 1) ? bf : (gate == 2) ? bg : bo;
    float s = 0.f;
    for (int e = 0; e < 512; e++) s += W[h * 512 + e] * be[e];
    g_bcomb[r] = s + bb[h];
}

__global__ void split_x_kernel(const float* __restrict__ x) {
    size_t i = ((size_t)blockIdx.x * 256 + threadIdx.x) * 4;
    store_split4(g_xh + i, g_xl + i, *(const float4*)(x + i));
}
__global__ void split_w_kernel() {
    size_t i = ((size_t)blockIdx.x * 256 + threadIdx.x) * 4;
    store_split4(g_wch + i, g_wcl + i, *(const float4*)(g_wcomb + i));
}
__global__ void split_h0_kernel(const float* __restrict__ h0) {
    size_t i = ((size_t)blockIdx.x * 256 + threadIdx.x) * 4;
    store_split4(g_hh[0] + i, g_hl[0] + i, *(const float4*)(h0 + i));
}
__global__ void split_R_kernel(const float* __restrict__ Ri, const float* __restrict__ Rf,
                               const float* __restrict__ Rg, const float* __restrict__ Ro) {
    size_t i = (size_t)blockIdx.x * 256 + threadIdx.x;   // 262144 quads
    int r = (int)(i >> 7), k = (int)(i & 127) * 4;
    int hc = r >> 6, w = r & 63, gate = w >> 4, j = w & 15;
    int h = hc * 16 + j;
    const float* R = (gate == 0) ? Ri : (gate == 1) ? Rf : (gate == 2) ? Rg : Ro;
    float4 v = *(const float4*)(R + (size_t)h * 512 + k);
    store_split4(g_rph + (size_t)r * 512 + k, g_rpl + (size_t)r * 512 + k, v);
}

// ---------- xs GEMM: mma.sync split-fp16 ----------
// C[65536,2048] = X @ Wcomb^T + bcomb. grid(16,512): bn=blockIdx.x*128, bm=blockIdx.y*128.
// smem halves: A buf0 @0, A buf1 @9216, B buf0 @18432, B buf1 @27648 (stride 72 halves/row)
#define XS_SMEM 73728
__global__ void __launch_bounds__(256) xs_mm_kernel() {
    extern __shared__ __half xsm[];
    uint32_t sb = smem_u32(xsm);
    const int tid = threadIdx.x, lane = tid & 31, wid = tid >> 5;
    const int bn = blockIdx.x * 128, bm = blockIdx.y * 128;
    const int wm = (wid & 1) * 64, wn = (wid >> 1) * 32;

    float acc[4][4][4] = {};

    auto load_chunk = [&](int cc) {
        int term = cc >> 2, kc = (cc & 3) * 64, buf = cc & 1;
        const __half* Asrc = (term == 2) ? g_xl : g_xh;
        const __half* Bsrc = (term == 1) ? g_wcl : g_wch;
#pragma unroll
        for (int q = 0; q < 4; q++) {
            int idx = tid + q * 256, r = idx >> 3, u = idx & 7;
            cpa16(sb + (buf * 9216 + r * 72 + u * 8) * 2, Asrc + (size_t)(bm + r) * 256 + kc + u * 8);
        }
#pragma unroll
        for (int q = 0; q < 4; q++) {
            int idx = tid + q * 256, r = idx >> 3, u = idx & 7;
            cpa16(sb + (18432 + buf * 9216 + r * 72 + u * 8) * 2, Bsrc + (size_t)(bn + r) * 256 + kc + u * 8);
        }
    };

    load_chunk(0);
    CP_COMMIT();
    for (int cc = 0; cc < 12; cc++) {
        if (cc < 11) { load_chunk(cc + 1); CP_COMMIT(); CP_WAIT(1); }
        else         { CP_WAIT(0); }
        __syncthreads();
        const int buf = cc & 1;
        const uint32_t abase = sb + (buf * 9216) * 2;
        const uint32_t bbase = sb + (18432 + buf * 9216) * 2;
#pragma unroll
        for (int kk = 0; kk < 64; kk += 16) {
            uint32_t a[4][4];
#pragma unroll
            for (int i = 0; i < 4; i++)
                ldm_x4(a[i], abase + ((wm + i * 16 + (lane & 15)) * 72 + kk + ((lane >> 4) << 3)) * 2);
#pragma unroll
            for (int f = 0; f < 4; f++) {
                uint32_t b0, b1;
                ldm_x2(b0, b1, bbase + ((wn + f * 8 + (lane & 7)) * 72 + kk + (((lane >> 3) & 1) << 3)) * 2);
#pragma unroll
                for (int i = 0; i < 4; i++) mma16816(acc[i][f], a[i], b0, b1);
            }
        }
        __syncthreads();
    }

    const int gate = bn >> 9, hb = bn & 511;
#pragma unroll
    for (int f = 0; f < 4; f++) {
        int nl = wn + f * 8 + (lane & 3) * 2;
        float b0v = g_bcomb[bn + nl], b1v = g_bcomb[bn + nl + 1];
#pragma unroll
        for (int i = 0; i < 4; i++) {
            int m0 = bm + wm + i * 16 + (lane >> 2);
#pragma unroll
            for (int rr = 0; rr < 2; rr++) {
                int m = m0 + rr * 8;
                int t = m & 511, b = m >> 9;
                float2 v = make_float2(acc[i][f][rr * 2 + 0] + b0v, acc[i][f][rr * 2 + 1] + b1v);
                *(float2*)(g_xs + (((size_t)t * 4 + gate) * 128 + b) * 512 + hb + nl) = v;
            }
        }
    }
}

// ---------- persistent scan: mma.sync split-fp16 ----------
// 128 blocks x 256 thr. Block = (bchunk=bid>>5 -> 32 batches, hchunk=bid&31 -> 16 h-cols x 4 gates = N64)
// smem halves: R hi @0 (64x520), R lo @33280, h hi @66560 (32x520), h lo @83200; acc_s floats @byte 199680
#define RS_LO 33280
#define HS_HI 66560
#define HS_LO 83200
#define ACC_B 199680
#define SC_SMEM 208128
__global__ void __launch_bounds__(256, 1) scan_mm_kernel(const float* __restrict__ c0,
                                                         float* __restrict__ out) {
    extern __shared__ __half ssm[];
    uint32_t sb = smem_u32(ssm);
    float* accs = (float*)((char*)ssm + ACC_B);
    const int tid = threadIdx.x, lane = tid & 31, wid = tid >> 5;
    const int bchunk = blockIdx.x >> 5, hchunk = blockIdx.x & 31;
    const int b0 = bchunk * 32;
    const int wm = (wid & 1) * 16, wn = (wid >> 1) * 16;

    // R resident
#pragma unroll
    for (int q = 0; q < 32; q++) {
        int idx = tid + q * 256;
        int part = idx >> 12, w = idx & 4095, r = w >> 6, u = w & 63;
        const __half* src = (part ? g_rpl : g_rph) + (size_t)(hchunk * 64 + r) * 512 + u * 8;
        *(uint4*)((char*)ssm + (part * RS_LO + r * 520 + u * 8) * 2) = *(const uint4*)src;
    }
    __syncthreads();

    float creg[2], hlast[2];
#pragma unroll
    for (int s = 0; s < 2; s++) {
        int q = tid + s * 256;
        int bl = q >> 4, hl = q & 15;
        creg[s] = c0[(b0 + bl) * 512 + hchunk * 16 + hl];
        hlast[s] = 0.f;
    }

    for (int t = 0; t < 512; t++) {
        const __half* hhp = g_hh[t & 1];
        const __half* hlp = g_hl[t & 1];
#pragma unroll
        for (int q = 0; q < 16; q++) {
            int idx = tid + q * 256;
            int part = idx >> 11, w = idx & 2047, r = w >> 6, u = w & 63;
            const __half* src = (part ? hlp : hhp) + (size_t)(b0 + r) * 512 + u * 8;
            cpa16(sb + ((part ? HS_LO : HS_HI) + r * 520 + u * 8) * 2, src);
        }
        CP_COMMIT();
        CP_WAIT(0);
        __syncthreads();

        float acc[2][4] = {};
        const uint32_t arow = (wm + (lane & 15)) * 520 + ((lane >> 4) << 3);
        const uint32_t brow0 = (wn + (lane & 7)) * 520 + (((lane >> 3) & 1) << 3);
#pragma unroll 4
        for (int kk = 0; kk < 512; kk += 16) {
            uint32_t a[4], b0, b1;
            ldm_x4(a, sb + (HS_HI + arow + kk) * 2);                 // A hi
#pragma unroll
            for (int f = 0; f < 2; f++) {
                ldm_x2(b0, b1, sb + (brow0 + f * 8 * 520 + kk) * 2);          // R hi
                mma16816(acc[f], a, b0, b1);
                ldm_x2(b0, b1, sb + (RS_LO + brow0 + f * 8 * 520 + kk) * 2);  // R lo
                mma16816(acc[f], a, b0, b1);
            }
            ldm_x4(a, sb + (HS_LO + arow + kk) * 2);                 // A lo
#pragma unroll
            for (int f = 0; f < 2; f++) {
                ldm_x2(b0, b1, sb + (brow0 + f * 8 * 520 + kk) * 2);          // R hi
                mma16816(acc[f], a, b0, b1);
            }
        }

        // stage accums: accs[n][m], n=gate*16+hl (0..63), m=b local (0..31), stride 33
#pragma unroll
        for (int f = 0; f < 2; f++) {
            int nl = wn + f * 8 + (lane & 3) * 2;
            int ml = wm + (lane >> 2);
            accs[nl * 33 + ml] = acc[f][0];
            accs[(nl + 1) * 33 + ml] = acc[f][1];
            accs[nl * 33 + ml + 8] = acc[f][2];
            accs[(nl + 1) * 33 + ml + 8] = acc[f][3];
        }
        __syncthreads();

        __half* hhn = g_hh[(t + 1) & 1];
        __half* hln = g_hl[(t + 1) & 1];
#pragma unroll
        for (int s = 0; s < 2; s++) {
            int q = tid + s * 256;
            int bl = q >> 4, hl = q & 15;
            int b = b0 + bl, h = hchunk * 16 + hl;
            const float* xsb = g_xs + (size_t)t * 262144 + (size_t)b * 512 + h;
            float ip = accs[(0 + hl) * 33 + bl]  + xsb[0];
            float fp = accs[(16 + hl) * 33 + bl] + xsb[65536];
            float gp = accs[(32 + hl) * 33 + bl] + xsb[131072];
            float op = accs[(48 + hl) * 33 + bl] + xsb[196608];
            float ig = 1.f / (1.f + expf(-ip));
            float fg = 1.f / (1.f + expf(-fp));
            float gv = tanhf(gp);
            float og = 1.f / (1.f + expf(-op));
            float cn = gv * ig + fg * creg[s];
            creg[s] = cn;
            float hn = og * tanhf(cn);
            hlast[s] = hn;
            out[((size_t)b * 512 + t) * 512 + h] = hn;
            __half hh_, hl_;
            split1(hn, hh_, hl_);
            hhn[b * 512 + h] = hh_;
            hln[b * 512 + h] = hl_;
        }

        __threadfence();
        __syncthreads();
        if (tid == 0) {
            atomicAdd(&g_cnt, 1u);
            unsigned tgt = (unsigned)(t + 1) * 128u;
            while (*(volatile unsigned*)&g_cnt < tgt) { }
        }
        __syncthreads();
    }

#pragma unroll
    for (int s = 0; s < 2; s++) {
        int q = tid + s * 256;
        int bl = q >> 4, hl = q & 15;
        size_t idx = (size_t)(b0 + bl) * 512 + hchunk * 16 + hl;
        out[33554432 + idx] = hlast[s];
        out[33619968 + idx] = creg[s];
    }
}

extern "C" void kernel_launch(void* const* d_in, const int* in_sizes, int n_in,
                              void* d_out, int out_size) {
    const float* x  = (const float*)d_in[0];
    const float* h0 = (const float*)d_in[1];
    const float* c0 = (const float*)d_in[2];
    const float* We = (const float*)d_in[3];
    const float* be = (const float*)d_in[4];
    const float* Wf = (const float*)d_in[5];
    const float* bf = (const float*)d_in[6];
    const float* Wi = (const float*)d_in[7];
    const float* bi = (const float*)d_in[8];
    const float* Wg = (const float*)d_in[9];
    const float* bg = (const float*)d_in[10];
    const float* Wo = (const float*)d_in[11];
    const float* bo = (const float*)d_in[12];
    const float* Rf = (const float*)d_in[13];
    const float* Ri = (const float*)d_in[14];
    const float* Rg = (const float*)d_in[15];
    const float* Ro = (const float*)d_in[16];
    float* out = (float*)d_out;

    cudaFuncSetAttribute(xs_mm_kernel, cudaFuncAttributeMaxDynamicSharedMemorySize, XS_SMEM);
    cudaFuncSetAttribute(scan_mm_kernel, cudaFuncAttributeMaxDynamicSharedMemorySize, SC_SMEM);

    reset_kernel<<<1, 1>>>();
    wcomb_kernel<<<dim3(4, 32), 256>>>(Wi, Wf, Wg, Wo, We);
    bcomb_kernel<<<8, 256>>>(Wi, Wf, Wg, Wo, be, bi, bf, bg, bo);
    split_x_kernel<<<16384, 256>>>(x);
    split_w_kernel<<<512, 256>>>();
    split_h0_kernel<<<64, 256>>>(h0);
    split_R_kernel<<<1024, 256>>>(Ri, Rf, Rg, Ro);
    xs_mm_kernel<<<dim3(16, 512), 256, XS_SMEM>>>();
    scan_mm_kernel<<<128, 256, SC_SMEM>>>(c0, out);
}

// round 7
// speedup vs baseline: 4.3540x; 1.2323x over previous
#include <cuda_runtime.h>
#include <cuda_fp16.h>
#include <cstdint>

// B=128, T=512, DIM=256, E=512, H=512
// out = hidden_seq(33554432) + h_last at 33554432 + c_last at 33619968

__device__ __align__(16) float g_wcomb[2048 * 256];
__device__ __align__(16) float g_bcomb[2048];
__device__ __align__(16) float g_xs[134217728];      // [t][gate][b][h] fp32
__device__ __align__(16) __half g_xh[16777216];      // X hi [65536][256]
__device__ __align__(16) __half g_xl[16777216];      // X lo
__device__ __align__(16) __half g_wch[524288];       // Wcomb hi [2048][256]
__device__ __align__(16) __half g_wcl[524288];       // Wcomb lo
__device__ __align__(16) __half g_rph[1048576];      // R packed hi [2048][512]; row=hc*64+gate*16+j <-> Rgate[hc*16+j]
__device__ __align__(16) __half g_rpl[1048576];      // R packed lo
__device__ __align__(16) __half g_hh[2][65536];      // h hi double buffer [b][k]
__device__ __align__(16) __half g_hl[2][65536];      // h lo
__device__ unsigned g_cnt4[128];                     // 4 group counters, stride 32 (128B apart)

// ---------- helpers ----------
__device__ __forceinline__ uint32_t smem_u32(const void* p) {
    uint32_t a;
    asm("{ .reg .u64 t; cvta.to.shared.u64 t, %1; cvt.u32.u64 %0, t; }" : "=r"(a) : "l"(p));
    return a;
}
__device__ __forceinline__ void ldm_x4(uint32_t* a, uint32_t addr) {
    asm volatile("ldmatrix.sync.aligned.m8n8.x4.shared.b16 {%0,%1,%2,%3}, [%4];"
                 : "=r"(a[0]), "=r"(a[1]), "=r"(a[2]), "=r"(a[3]) : "r"(addr));
}
__device__ __forceinline__ void mma16816(float* d, const uint32_t* a, uint32_t b0, uint32_t b1) {
    asm volatile("mma.sync.aligned.m16n8k16.row.col.f32.f16.f16.f32 "
                 "{%0,%1,%2,%3},{%4,%5,%6,%7},{%8,%9},{%0,%1,%2,%3};"
                 : "+f"(d[0]), "+f"(d[1]), "+f"(d[2]), "+f"(d[3])
                 : "r"(a[0]), "r"(a[1]), "r"(a[2]), "r"(a[3]), "r"(b0), "r"(b1));
}
__device__ __forceinline__ void cpa16(uint32_t saddr, const void* g) {
    asm volatile("cp.async.cg.shared.global [%0], [%1], 16;" :: "r"(saddr), "l"(g));
}
#define CP_COMMIT() asm volatile("cp.async.commit_group;" ::: "memory")
#define CP_WAIT(N)  asm volatile("cp.async.wait_group %0;" :: "n"(N) : "memory")

__device__ __forceinline__ void split1(float v, __half& h, __half& l) {
    h = __float2half_rn(v);
    l = __float2half_rn(v - __half2float(h));
}
__device__ __forceinline__ void store_split4(__half* dh, __half* dl, float4 v) {
    __half h0, h1, h2, h3, l0, l1, l2, l3;
    split1(v.x, h0, l0); split1(v.y, h1, l1); split1(v.z, h2, l2); split1(v.w, h3, l3);
    ((__half2*)dh)[0] = __halves2half2(h0, h1);
    ((__half2*)dh)[1] = __halves2half2(h2, h3);
    ((__half2*)dl)[0] = __halves2half2(l0, l1);
    ((__half2*)dl)[1] = __halves2half2(l2, l3);
}

// ---------- prep kernels ----------
__global__ void reset_kernel() {
    if (threadIdx.x < 128) g_cnt4[threadIdx.x] = 0u;
}

__global__ void wcomb_kernel(const float* __restrict__ Wi, const float* __restrict__ Wf,
                             const float* __restrict__ Wg, const float* __restrict__ Wo,
                             const float* __restrict__ We) {
    __shared__ float As[16][65];
    __shared__ float Bs[16][65];
    const int bm = blockIdx.y * 64, bn = blockIdx.x * 64, tid = threadIdx.x;
    const int tx = tid % 16, ty = tid / 16;
    float acc[4][4] = {};
    for (int k0 = 0; k0 < 512; k0 += 16) {
        for (int i = tid; i < 1024; i += 256) {
            int r = i / 16, kk = i % 16, row = bm + r, gate = row >> 9, h = row & 511;
            const float* W = (gate == 0) ? Wi : (gate == 1) ? Wf : (gate == 2) ? Wg : Wo;
            As[kk][r] = W[h * 512 + k0 + kk];
        }
        for (int i = tid; i < 1024; i += 256) {
            int kk = i / 64, c = i % 64;
            Bs[kk][c] = We[(k0 + kk) * 256 + bn + c];
        }
        __syncthreads();
#pragma unroll
        for (int kk = 0; kk < 16; kk++) {
            float a[4], b[4];
#pragma unroll
            for (int i = 0; i < 4; i++) a[i] = As[kk][ty * 4 + i];
#pragma unroll
            for (int j = 0; j < 4; j++) b[j] = Bs[kk][tx * 4 + j];
#pragma unroll
            for (int i = 0; i < 4; i++)
#pragma unroll
                for (int j = 0; j < 4; j++) acc[i][j] += a[i] * b[j];
        }
        __syncthreads();
    }
#pragma unroll
    for (int i = 0; i < 4; i++)
#pragma unroll
        for (int j = 0; j < 4; j++)
            g_wcomb[(bm + ty * 4 + i) * 256 + bn + tx * 4 + j] = acc[i][j];
}

__global__ void bcomb_kernel(const float* __restrict__ Wi, const float* __restrict__ Wf,
                             const float* __restrict__ Wg, const float* __restrict__ Wo,
                             const float* __restrict__ be,
                             const float* __restrict__ bi, const float* __restrict__ bf,
                             const float* __restrict__ bg, const float* __restrict__ bo) {
    int r = blockIdx.x * 256 + threadIdx.x;
    if (r >= 2048) return;
    int gate = r >> 9, h = r & 511;
    const float* W = (gate == 0) ? Wi : (gate == 1) ? Wf : (gate == 2) ? Wg : Wo;
    const float* bb = (gate == 0) ? bi : (gate == 1) ? bf : (gate == 2) ? bg : bo;
    float s = 0.f;
    for (int e = 0; e < 512; e++) s += W[h * 512 + e] * be[e];
    g_bcomb[r] = s + bb[h];
}

__global__ void split_x_kernel(const float* __restrict__ x) {
    size_t i = ((size_t)blockIdx.x * 256 + threadIdx.x) * 4;
    store_split4(g_xh + i, g_xl + i, *(const float4*)(x + i));
}
__global__ void split_w_kernel() {
    size_t i = ((size_t)blockIdx.x * 256 + threadIdx.x) * 4;
    store_split4(g_wch + i, g_wcl + i, *(const float4*)(g_wcomb + i));
}
__global__ void split_h0_kernel(const float* __restrict__ h0) {
    size_t i = ((size_t)blockIdx.x * 256 + threadIdx.x) * 4;
    store_split4(g_hh[0] + i, g_hl[0] + i, *(const float4*)(h0 + i));
}
__global__ void split_R_kernel(const float* __restrict__ Ri, const float* __restrict__ Rf,
                               const float* __restrict__ Rg, const float* __restrict__ Ro) {
    size_t i = (size_t)blockIdx.x * 256 + threadIdx.x;   // 262144 quads
    int r = (int)(i >> 7), k = (int)(i & 127) * 4;
    int hc = r >> 6, w = r & 63, gate = w >> 4, j = w & 15;
    int h = hc * 16 + j;
    const float* R = (gate == 0) ? Ri : (gate == 1) ? Rf : (gate == 2) ? Rg : Ro;
    float4 v = *(const float4*)(R + (size_t)h * 512 + k);
    store_split4(g_rph + (size_t)r * 512 + k, g_rpl + (size_t)r * 512 + k, v);
}

// ---------- xs GEMM: mma.sync split-fp16, single-load K-chunks ----------
// C[65536,2048] = X @ Wcomb^T + bcomb. grid(16,512): bn=blockIdx.x*128, bm=blockIdx.y*128.
// per buf (halves): Ah @0, Al @9216, Bh @18432, Bl @27648; buf stride 36864. stride 72/row.
#define XS_SMEM 147456
__global__ void __launch_bounds__(256) xs_mm_kernel() {
    extern __shared__ __half xsm[];
    uint32_t sb = smem_u32(xsm);
    const int tid = threadIdx.x, lane = tid & 31, wid = tid >> 5;
    const int bn = blockIdx.x * 128, bm = blockIdx.y * 128;
    const int wm = (wid & 1) * 64, wn = (wid >> 1) * 32;

    float acc[4][4][4] = {};

    auto load_kc = [&](int kc) {
        uint32_t base = (kc & 1) * 36864;
        const int kcol = kc * 64;
#pragma unroll
        for (int q = 0; q < 4; q++) {
            int idx = tid + q * 256, r = idx >> 3, u = idx & 7;
            size_t ga = (size_t)(bm + r) * 256 + kcol + u * 8;
            size_t gb = (size_t)(bn + r) * 256 + kcol + u * 8;
            uint32_t so = (base + r * 72 + u * 8) * 2;
            cpa16(sb + so, g_xh + ga);
            cpa16(sb + so + 18432, g_xl + ga);
            cpa16(sb + so + 36864, g_wch + gb);
            cpa16(sb + so + 55296, g_wcl + gb);
        }
    };

    load_kc(0);
    CP_COMMIT();
    for (int kc = 0; kc < 4; kc++) {
        if (kc < 3) { load_kc(kc + 1); CP_COMMIT(); CP_WAIT(1); }
        else        { CP_WAIT(0); }
        __syncthreads();
        const uint32_t ah = sb + ((kc & 1) * 36864) * 2;
        const uint32_t al = ah + 18432, bhb = ah + 36864, blb = ah + 55296;
        const uint32_t aoff = (wm + (lane & 15)) * 72 + ((lane >> 4) << 3);
        const uint32_t boff0 = (wn + ((lane >> 4) << 3) + (lane & 7)) * 72 + (((lane >> 3) & 1) << 3);
        const uint32_t boff1 = boff0 + 16 * 72;
#pragma unroll
        for (int kk = 0; kk < 64; kk += 16) {
            uint32_t bh01[4], bh23[4], bl01[4], bl23[4];
            ldm_x4(bh01, bhb + (boff0 + kk) * 2);
            ldm_x4(bh23, bhb + (boff1 + kk) * 2);
            ldm_x4(bl01, blb + (boff0 + kk) * 2);
            ldm_x4(bl23, blb + (boff1 + kk) * 2);
#pragma unroll
            for (int i = 0; i < 4; i++) {
                uint32_t ahi[4], alo[4];
                ldm_x4(ahi, ah + (aoff + i * 16 * 72 + kk) * 2);
                ldm_x4(alo, al + (aoff + i * 16 * 72 + kk) * 2);
                mma16816(acc[i][0], ahi, bh01[0], bh01[1]);
                mma16816(acc[i][1], ahi, bh01[2], bh01[3]);
                mma16816(acc[i][2], ahi, bh23[0], bh23[1]);
                mma16816(acc[i][3], ahi, bh23[2], bh23[3]);
                mma16816(acc[i][0], ahi, bl01[0], bl01[1]);
                mma16816(acc[i][1], ahi, bl01[2], bl01[3]);
                mma16816(acc[i][2], ahi, bl23[0], bl23[1]);
                mma16816(acc[i][3], ahi, bl23[2], bl23[3]);
                mma16816(acc[i][0], alo, bh01[0], bh01[1]);
                mma16816(acc[i][1], alo, bh01[2], bh01[3]);
                mma16816(acc[i][2], alo, bh23[0], bh23[1]);
                mma16816(acc[i][3], alo, bh23[2], bh23[3]);
            }
        }
        __syncthreads();
    }

    const int gate = bn >> 9, hb = bn & 511;
#pragma unroll
    for (int f = 0; f < 4; f++) {
        int nl = wn + f * 8 + (lane & 3) * 2;
        float b0v = g_bcomb[bn + nl], b1v = g_bcomb[bn + nl + 1];
#pragma unroll
        for (int i = 0; i < 4; i++) {
            int m0 = bm + wm + i * 16 + (lane >> 2);
#pragma unroll
            for (int rr = 0; rr < 2; rr++) {
                int m = m0 + rr * 8;
                int t = m & 511, b = m >> 9;
                float2 v = make_float2(acc[i][f][rr * 2 + 0] + b0v, acc[i][f][rr * 2 + 1] + b1v);
                *(float2*)(g_xs + (((size_t)t * 4 + gate) * 128 + b) * 512 + hb + nl) = v;
            }
        }
    }
}

// ---------- persistent scan: mma.sync split-fp16, staged loads + group barriers ----------
// 128 blocks x 256 thr. Block=(bchunk=bid>>5: 32 batches, hchunk=bid&31: 16 h x 4 gates = N64).
// smem halves: Rhi @0 (64x520), Rlo @33280, h hi @66560 (32x520), h lo @83200.
// bytes: accs @199680 (64x33 f32), xsbuf @208128 (128x16 f32). total 216320.
#define RS_LO 33280
#define HS_HI 66560
#define HS_LO 83200
#define ACC_B 199680
#define XSB_B 208128
#define SC_SMEM 216320
__global__ void __launch_bounds__(256, 1) scan_mm_kernel(const float* __restrict__ c0,
                                                         float* __restrict__ out) {
    extern __shared__ __half ssm[];
    uint32_t sb = smem_u32(ssm);
    float* accs = (float*)((char*)ssm + ACC_B);
    float* xsf = (float*)((char*)ssm + XSB_B);
    const int tid = threadIdx.x, lane = tid & 31, wid = tid >> 5;
    const int bchunk = blockIdx.x >> 5, hchunk = blockIdx.x & 31;
    const int b0 = bchunk * 32;
    const int wm = (wid & 1) * 16, wn = (wid >> 1) * 16;

    // R resident (hi + lo)
#pragma unroll
    for (int q = 0; q < 32; q++) {
        int idx = tid + q * 256;
        int part = idx >> 12, w = idx & 4095, r = w >> 6, u = w & 63;
        const __half* src = (part ? g_rpl : g_rph) + (size_t)(hchunk * 64 + r) * 512 + u * 8;
        *(uint4*)((char*)ssm + (part * RS_LO + r * 520 + u * 8) * 2) = *(const uint4*)src;
    }
    __syncthreads();

    float creg[2], hlast[2];
#pragma unroll
    for (int s = 0; s < 2; s++) {
        int q = tid + s * 256;
        int bl = q >> 4, hl = q & 15;
        creg[s] = c0[(b0 + bl) * 512 + hchunk * 16 + hl];
        hlast[s] = 0.f;
    }

    const uint32_t arow = (wm + (lane & 15)) * 520 + ((lane >> 4) << 3);
    const uint32_t brow = (wn + ((lane >> 4) << 3) + (lane & 7)) * 520 + (((lane >> 3) & 1) << 3);

    for (int t = 0; t < 512; t++) {
        const __half* hhp = g_hh[t & 1];
        const __half* hlp = g_hl[t & 1];

        auto load_h = [&](int c) {
#pragma unroll
            for (int q = 0; q < 4; q++) {
                int idx = tid + q * 256;
                int part = idx >> 9, w = idx & 511, r = w >> 4, u = w & 15;
                const __half* src = (part ? hlp : hhp) + (size_t)(b0 + r) * 512 + c * 128 + u * 8;
                cpa16(sb + ((part ? HS_LO : HS_HI) + r * 520 + c * 128 + u * 8) * 2, src);
            }
        };
        load_h(0); CP_COMMIT();
        load_h(1); CP_COMMIT();
        // xs prefetch for pointwise (independent of h)
#pragma unroll
        for (int q = 0; q < 2; q++) {
            int idx = tid + q * 256;
            int gate = idx >> 7, w = idx & 127, bl = w >> 2, p = w & 3;
            const float* src = g_xs + (size_t)t * 262144 + (size_t)gate * 65536
                             + (size_t)(b0 + bl) * 512 + hchunk * 16 + p * 4;
            cpa16(sb + XSB_B + ((gate * 32 + bl) * 16 + p * 4) * 4, src);
        }
        CP_COMMIT();
        load_h(2); CP_COMMIT();
        load_h(3); CP_COMMIT();

        float acc[2][4] = {};
        auto chunk = [&](int c) {
            const int kb = c * 128;
#pragma unroll
            for (int k8 = 0; k8 < 8; k8++) {
                int kk = kb + k8 * 16;
                uint32_t ahi[4], alo[4], bh[4], blv[4];
                ldm_x4(ahi, sb + (HS_HI + arow + kk) * 2);
                ldm_x4(alo, sb + (HS_LO + arow + kk) * 2);
                ldm_x4(bh, sb + (brow + kk) * 2);
                ldm_x4(blv, sb + (RS_LO + brow + kk) * 2);
                mma16816(acc[0], ahi, bh[0], bh[1]);
                mma16816(acc[1], ahi, bh[2], bh[3]);
                mma16816(acc[0], ahi, blv[0], blv[1]);
                mma16816(acc[1], ahi, blv[2], blv[3]);
                mma16816(acc[0], alo, bh[0], bh[1]);
                mma16816(acc[1], alo, bh[2], bh[3]);
            }
        };
        CP_WAIT(4); __syncthreads(); chunk(0);
        CP_WAIT(3); __syncthreads(); chunk(1);
        CP_WAIT(1); __syncthreads(); chunk(2);
        CP_WAIT(0); __syncthreads(); chunk(3);

        // stage accums: accs[n][m], n = gate16 group col (0..63), m = b local, stride 33
#pragma unroll
        for (int f = 0; f < 2; f++) {
            int nl = wn + f * 8 + (lane & 3) * 2;
            int ml = wm + (lane >> 2);
            accs[nl * 33 + ml] = acc[f][0];
            accs[(nl + 1) * 33 + ml] = acc[f][1];
            accs[nl * 33 + ml + 8] = acc[f][2];
            accs[(nl + 1) * 33 + ml + 8] = acc[f][3];
        }
        __syncthreads();

        __half* hhn = g_hh[(t + 1) & 1];
        __half* hln = g_hl[(t + 1) & 1];
#pragma unroll
        for (int s = 0; s < 2; s++) {
            int q = tid + s * 256;
            int bl = q >> 4, hl = q & 15;
            int b = b0 + bl, h = hchunk * 16 + hl;
            float ip = accs[(0 + hl) * 33 + bl]  + xsf[(0 * 32 + bl) * 16 + hl];
            float fp = accs[(16 + hl) * 33 + bl] + xsf[(1 * 32 + bl) * 16 + hl];
            float gp = accs[(32 + hl) * 33 + bl] + xsf[(2 * 32 + bl) * 16 + hl];
            float op = accs[(48 + hl) * 33 + bl] + xsf[(3 * 32 + bl) * 16 + hl];
            float ig = 1.f / (1.f + expf(-ip));
            float fg = 1.f / (1.f + expf(-fp));
            float gv = tanhf(gp);
            float og = 1.f / (1.f + expf(-op));
            float cn = gv * ig + fg * creg[s];
            creg[s] = cn;
            float hn = og * tanhf(cn);
            hlast[s] = hn;
            out[((size_t)b * 512 + t) * 512 + h] = hn;
            __half hh_, hl_;
            split1(hn, hh_, hl_);
            hhn[b * 512 + h] = hh_;
            hln[b * 512 + h] = hl_;
        }

        // per-bchunk barrier (32 blocks share data; 4 independent groups)
        __threadfence();
        __syncthreads();
        if (tid == 0) {
            unsigned tgt = (unsigned)(t + 1) * 32u;
            atomicAdd(&g_cnt4[bchunk * 32], 1u);
            while (*(volatile unsigned*)&g_cnt4[bchunk * 32] < tgt) { __nanosleep(32); }
        }
        __syncthreads();
    }

#pragma unroll
    for (int s = 0; s < 2; s++) {
        int q = tid + s * 256;
        int bl = q >> 4, hl = q & 15;
        size_t idx = (size_t)(b0 + bl) * 512 + hchunk * 16 + hl;
        out[33554432 + idx] = hlast[s];
        out[33619968 + idx] = creg[s];
    }
}

extern "C" void kernel_launch(void* const* d_in, const int* in_sizes, int n_in,
                              void* d_out, int out_size) {
    const float* x  = (const float*)d_in[0];
    const float* h0 = (const float*)d_in[1];
    const float* c0 = (const float*)d_in[2];
    const float* We = (const float*)d_in[3];
    const float* be = (const float*)d_in[4];
    const float* Wf = (const float*)d_in[5];
    const float* bf = (const float*)d_in[6];
    const float* Wi = (const float*)d_in[7];
    const float* bi = (const float*)d_in[8];
    const float* Wg = (const float*)d_in[9];
    const float* bg = (const float*)d_in[10];
    const float* Wo = (const float*)d_in[11];
    const float* bo = (const float*)d_in[12];
    const float* Rf = (const float*)d_in[13];
    const float* Ri = (const float*)d_in[14];
    const float* Rg = (const float*)d_in[15];
    const float* Ro = (const float*)d_in[16];
    float* out = (float*)d_out;

    cudaFuncSetAttribute(xs_mm_kernel, cudaFuncAttributeMaxDynamicSharedMemorySize, XS_SMEM);
    cudaFuncSetAttribute(scan_mm_kernel, cudaFuncAttributeMaxDynamicSharedMemorySize, SC_SMEM);

    reset_kernel<<<1, 128>>>();
    wcomb_kernel<<<dim3(4, 32), 256>>>(Wi, Wf, Wg, Wo, We);
    bcomb_kernel<<<8, 256>>>(Wi, Wf, Wg, Wo, be, bi, bf, bg, bo);
    split_x_kernel<<<16384, 256>>>(x);
    split_w_kernel<<<512, 256>>>();
    split_h0_kernel<<<64, 256>>>(h0);
    split_R_kernel<<<1024, 256>>>(Ri, Rf, Rg, Ro);
    xs_mm_kernel<<<dim3(16, 512), 256, XS_SMEM>>>();
    scan_mm_kernel<<<128, 256, SC_SMEM>>>(c0, out);
}

// round 11
// speedup vs baseline: 5.0325x; 1.1558x over previous
#include <cuda_runtime.h>
#include <cuda_fp16.h>
#include <cstdint>

// B=128, T=512, DIM=256, E=512, H=512
// out = hidden_seq(33554432) + h_last at 33554432 + c_last at 33619968

__device__ __align__(16) float g_wcomb[2048 * 256];
__device__ __align__(16) float g_bcomb[2048];
__device__ __align__(16) float g_xs[134217728];      // [t][gate][b][h] fp32
__device__ __align__(16) __half g_xh[16777216];      // X hi [65536][256]
__device__ __align__(16) __half g_xl[16777216];      // X lo
__device__ __align__(16) __half g_wch[524288];       // Wcomb hi [2048][256]
__device__ __align__(16) __half g_wcl[524288];       // Wcomb lo
__device__ __align__(16) __half g_rph[1048576];      // R packed hi [2048][512]; row=hc*64+gate*16+j <-> Rgate[hc*16+j]
__device__ __align__(16) __half g_rpl[1048576];      // R packed lo
__device__ __align__(16) __half g_hh[2][65536];      // h (fp16) double buffer [b][k]
__device__ unsigned g_cnt4[128];                     // 4 group counters, stride 32 (128B apart)

// ---------- helpers ----------
__device__ __forceinline__ uint32_t smem_u32(const void* p) {
    uint32_t a;
    asm("{ .reg .u64 t; cvta.to.shared.u64 t, %1; cvt.u32.u64 %0, t; }" : "=r"(a) : "l"(p));
    return a;
}
__device__ __forceinline__ void ldm_x4(uint32_t* a, uint32_t addr) {
    asm volatile("ldmatrix.sync.aligned.m8n8.x4.shared.b16 {%0,%1,%2,%3}, [%4];"
                 : "=r"(a[0]), "=r"(a[1]), "=r"(a[2]), "=r"(a[3]) : "r"(addr));
}
__device__ __forceinline__ void mma16816(float* d, const uint32_t* a, uint32_t b0, uint32_t b1) {
    asm volatile("mma.sync.aligned.m16n8k16.row.col.f32.f16.f16.f32 "
                 "{%0,%1,%2,%3},{%4,%5,%6,%7},{%8,%9},{%0,%1,%2,%3};"
                 : "+f"(d[0]), "+f"(d[1]), "+f"(d[2]), "+f"(d[3])
                 : "r"(a[0]), "r"(a[1]), "r"(a[2]), "r"(a[3]), "r"(b0), "r"(b1));
}
__device__ __forceinline__ void cpa16(uint32_t saddr, const void* g) {
    asm volatile("cp.async.cg.shared.global [%0], [%1], 16;" :: "r"(saddr), "l"(g));
}
#define CP_COMMIT() asm volatile("cp.async.commit_group;" ::: "memory")
#define CP_WAIT(N)  asm volatile("cp.async.wait_group %0;" :: "n"(N) : "memory")

__device__ __forceinline__ void split1(float v, __half& h, __half& l) {
    h = __float2half_rn(v);
    l = __float2half_rn(v - __half2float(h));
}
__device__ __forceinline__ void store_split4(__half* dh, __half* dl, float4 v) {
    __half h0, h1, h2, h3, l0, l1, l2, l3;
    split1(v.x, h0, l0); split1(v.y, h1, l1); split1(v.z, h2, l2); split1(v.w, h3, l3);
    ((__half2*)dh)[0] = __halves2half2(h0, h1);
    ((__half2*)dh)[1] = __halves2half2(h2, h3);
    ((__half2*)dl)[0] = __halves2half2(l0, l1);
    ((__half2*)dl)[1] = __halves2half2(l2, l3);
}

// ---------- prep kernels ----------
__global__ void reset_kernel() {
    if (threadIdx.x < 128) g_cnt4[threadIdx.x] = 0u;
}

__global__ void wcomb_kernel(const float* __restrict__ Wi, const float* __restrict__ Wf,
                             const float* __restrict__ Wg, const float* __restrict__ Wo,
                             const float* __restrict__ We) {
    __shared__ float As[16][65];
    __shared__ float Bs[16][65];
    const int bm = blockIdx.y * 64, bn = blockIdx.x * 64, tid = threadIdx.x;
    const int tx = tid % 16, ty = tid / 16;
    float acc[4][4] = {};
    for (int k0 = 0; k0 < 512; k0 += 16) {
        for (int i = tid; i < 1024; i += 256) {
            int r = i / 16, kk = i % 16, row = bm + r, gate = row >> 9, h = row & 511;
            const float* W = (gate == 0) ? Wi : (gate == 1) ? Wf : (gate == 2) ? Wg : Wo;
            As[kk][r] = W[h * 512 + k0 + kk];
        }
        for (int i = tid; i < 1024; i += 256) {
            int kk = i / 64, c = i % 64;
            Bs[kk][c] = We[(k0 + kk) * 256 + bn + c];
        }
        __syncthreads();
#pragma unroll
        for (int kk = 0; kk < 16; kk++) {
            float a[4], b[4];
#pragma unroll
            for (int i = 0; i < 4; i++) a[i] = As[kk][ty * 4 + i];
#pragma unroll
            for (int j = 0; j < 4; j++) b[j] = Bs[kk][tx * 4 + j];
#pragma unroll
            for (int i = 0; i < 4; i++)
#pragma unroll
                for (int j = 0; j < 4; j++) acc[i][j] += a[i] * b[j];
        }
        __syncthreads();
    }
#pragma unroll
    for (int i = 0; i < 4; i++)
#pragma unroll
        for (int j = 0; j < 4; j++)
            g_wcomb[(bm + ty * 4 + i) * 256 + bn + tx * 4 + j] = acc[i][j];
}

__global__ void bcomb_kernel(const float* __restrict__ Wi, const float* __restrict__ Wf,
                             const float* __restrict__ Wg, const float* __restrict__ Wo,
                             const float* __restrict__ be,
                             const float* __restrict__ bi, const float* __restrict__ bf,
                             const float* __restrict__ bg, const float* __restrict__ bo) {
    int r = blockIdx.x * 256 + threadIdx.x;
    if (r >= 2048) return;
    int gate = r >> 9, h = r & 511;
    const float* W = (gate == 0) ? Wi : (gate == 1) ? Wf : (gate == 2) ? Wg : Wo;
    const float* bb = (gate == 0) ? bi : (gate == 1) ? bf : (gate == 2) ? bg : bo;
    float s = 0.f;
    for (int e = 0; e < 512; e++) s += W[h * 512 + e] * be[e];
    g_bcomb[r] = s + bb[h];
}

__global__ void split_x_kernel(const float* __restrict__ x) {
    size_t i = ((size_t)blockIdx.x * 256 + threadIdx.x) * 4;
    store_split4(g_xh + i, g_xl + i, *(const float4*)(x + i));
}
__global__ void split_w_kernel() {
    size_t i = ((size_t)blockIdx.x * 256 + threadIdx.x) * 4;
    store_split4(g_wch + i, g_wcl + i, *(const float4*)(g_wcomb + i));
}
__global__ void split_h0_kernel(const float* __restrict__ h0) {
    size_t i = ((size_t)blockIdx.x * 256 + threadIdx.x) * 4;
    float4 v = *(const float4*)(h0 + i);
    ((__half2*)(g_hh[0] + i))[0] = __floats2half2_rn(v.x, v.y);
    ((__half2*)(g_hh[0] + i))[1] = __floats2half2_rn(v.z, v.w);
}
__global__ void split_R_kernel(const float* __restrict__ Ri, const float* __restrict__ Rf,
                               const float* __restrict__ Rg, const float* __restrict__ Ro) {
    size_t i = (size_t)blockIdx.x * 256 + threadIdx.x;   // 262144 quads
    int r = (int)(i >> 7), k = (int)(i & 127) * 4;
    int hc = r >> 6, w = r & 63, gate = w >> 4, j = w & 15;
    int h = hc * 16 + j;
    const float* R = (gate == 0) ? Ri : (gate == 1) ? Rf : (gate == 2) ? Rg : Ro;
    float4 v = *(const float4*)(R + (size_t)h * 512 + k);
    store_split4(g_rph + (size_t)r * 512 + k, g_rpl + (size_t)r * 512 + k, v);
}

// ---------- xs GEMM: mma.sync split-fp16, single-load K-chunks (3 terms, unchanged) ----------
#define XS_SMEM 147456
__global__ void __launch_bounds__(256) xs_mm_kernel() {
    extern __shared__ __half xsm[];
    uint32_t sb = smem_u32(xsm);
    const int tid = threadIdx.x, lane = tid & 31, wid = tid >> 5;
    const int bn = blockIdx.x * 128, bm = blockIdx.y * 128;
    const int wm = (wid & 1) * 64, wn = (wid >> 1) * 32;

    float acc[4][4][4] = {};

    auto load_kc = [&](int kc) {
        uint32_t base = (kc & 1) * 36864;
        const int kcol = kc * 64;
#pragma unroll
        for (int q = 0; q < 4; q++) {
            int idx = tid + q * 256, r = idx >> 3, u = idx & 7;
            size_t ga = (size_t)(bm + r) * 256 + kcol + u * 8;
            size_t gb = (size_t)(bn + r) * 256 + kcol + u * 8;
            uint32_t so = (base + r * 72 + u * 8) * 2;
            cpa16(sb + so, g_xh + ga);
            cpa16(sb + so + 18432, g_xl + ga);
            cpa16(sb + so + 36864, g_wch + gb);
            cpa16(sb + so + 55296, g_wcl + gb);
        }
    };

    load_kc(0);
    CP_COMMIT();
    for (int kc = 0; kc < 4; kc++) {
        if (kc < 3) { load_kc(kc + 1); CP_COMMIT(); CP_WAIT(1); }
        else        { CP_WAIT(0); }
        __syncthreads();
        const uint32_t ah = sb + ((kc & 1) * 36864) * 2;
        const uint32_t al = ah + 18432, bhb = ah + 36864, blb = ah + 55296;
        const uint32_t aoff = (wm + (lane & 15)) * 72 + ((lane >> 4) << 3);
        const uint32_t boff0 = (wn + ((lane >> 4) << 3) + (lane & 7)) * 72 + (((lane >> 3) & 1) << 3);
        const uint32_t boff1 = boff0 + 16 * 72;
#pragma unroll
        for (int kk = 0; kk < 64; kk += 16) {
            uint32_t bh01[4], bh23[4], bl01[4], bl23[4];
            ldm_x4(bh01, bhb + (boff0 + kk) * 2);
            ldm_x4(bh23, bhb + (boff1 + kk) * 2);
            ldm_x4(bl01, blb + (boff0 + kk) * 2);
            ldm_x4(bl23, blb + (boff1 + kk) * 2);
#pragma unroll
            for (int i = 0; i < 4; i++) {
                uint32_t ahi[4], alo[4];
                ldm_x4(ahi, ah + (aoff + i * 16 * 72 + kk) * 2);
                ldm_x4(alo, al + (aoff + i * 16 * 72 + kk) * 2);
                mma16816(acc[i][0], ahi, bh01[0], bh01[1]);
                mma16816(acc[i][1], ahi, bh01[2], bh01[3]);
                mma16816(acc[i][2], ahi, bh23[0], bh23[1]);
                mma16816(acc[i][3], ahi, bh23[2], bh23[3]);
                mma16816(acc[i][0], ahi, bl01[0], bl01[1]);
                mma16816(acc[i][1], ahi, bl01[2], bl01[3]);
                mma16816(acc[i][2], ahi, bl23[0], bl23[1]);
                mma16816(acc[i][3], ahi, bl23[2], bl23[3]);
                mma16816(acc[i][0], alo, bh01[0], bh01[1]);
                mma16816(acc[i][1], alo, bh01[2], bh01[3]);
                mma16816(acc[i][2], alo, bh23[0], bh23[1]);
                mma16816(acc[i][3], alo, bh23[2], bh23[3]);
            }
        }
        __syncthreads();
    }

    const int gate = bn >> 9, hb = bn & 511;
#pragma unroll
    for (int f = 0; f < 4; f++) {
        int nl = wn + f * 8 + (lane & 3) * 2;
        float b0v = g_bcomb[bn + nl], b1v = g_bcomb[bn + nl + 1];
#pragma unroll
        for (int i = 0; i < 4; i++) {
            int m0 = bm + wm + i * 16 + (lane >> 2);
#pragma unroll
            for (int rr = 0; rr < 2; rr++) {
                int m = m0 + rr * 8;
                int t = m & 511, b = m >> 9;
                float2 v = make_float2(acc[i][f][rr * 2 + 0] + b0v, acc[i][f][rr * 2 + 1] + b1v);
                *(float2*)(g_xs + (((size_t)t * 4 + gate) * 128 + b) * 512 + hb + nl) = v;
            }
        }
    }
}

// ---------- persistent scan: 2-term split (Ah*Bh + Ah*Bl), h stored as plain fp16 ----------
// 128 blocks x 256 thr. Block=(bchunk: 32 batches, hchunk: 16 h x 4 gates = N64).
// smem halves: Rhi @0 (64x520), Rlo @33280, h @66560 (32x520).
// bytes: accs @199680 (64x33 f32), xsbuf @208128 (128x16 f32). total 216320.
#define RS_LO 33280
#define HS_HI 66560
#define ACC_B 199680
#define XSB_B 208128
#define SC_SMEM 216320
__global__ void __launch_bounds__(256, 1) scan_mm_kernel(const float* __restrict__ c0,
                                                         float* __restrict__ out) {
    extern __shared__ __half ssm[];
    uint32_t sb = smem_u32(ssm);
    float* accs = (float*)((char*)ssm + ACC_B);
    float* xsf = (float*)((char*)ssm + XSB_B);
    const int tid = threadIdx.x, lane = tid & 31, wid = tid >> 5;
    const int bchunk = blockIdx.x >> 5, hchunk = blockIdx.x & 31;
    const int b0 = bchunk * 32;
    const int wm = (wid & 1) * 16, wn = (wid >> 1) * 16;

    // R resident (hi + lo)
#pragma unroll
    for (int q = 0; q < 32; q++) {
        int idx = tid + q * 256;
        int part = idx >> 12, w = idx & 4095, r = w >> 6, u = w & 63;
        const __half* src = (part ? g_rpl : g_rph) + (size_t)(hchunk * 64 + r) * 512 + u * 8;
        *(uint4*)((char*)ssm + (part * RS_LO + r * 520 + u * 8) * 2) = *(const uint4*)src;
    }
    __syncthreads();

    float creg[2], hlast[2];
#pragma unroll
    for (int s = 0; s < 2; s++) {
        int q = tid + s * 256;
        int bl = q >> 4, hl = q & 15;
        creg[s] = c0[(b0 + bl) * 512 + hchunk * 16 + hl];
        hlast[s] = 0.f;
    }

    const uint32_t arow = (wm + (lane & 15)) * 520 + ((lane >> 4) << 3);
    const uint32_t brow = (wn + ((lane >> 4) << 3) + (lane & 7)) * 520 + (((lane >> 3) & 1) << 3);

    for (int t = 0; t < 512; t++) {
        const __half* hhp = g_hh[t & 1];

        auto load_h = [&](int c) {
#pragma unroll
            for (int q = 0; q < 2; q++) {
                int idx = tid + q * 256;
                int r = idx >> 4, u = idx & 15;
                const __half* src = hhp + (size_t)(b0 + r) * 512 + c * 128 + u * 8;
                cpa16(sb + (HS_HI + r * 520 + c * 128 + u * 8) * 2, src);
            }
        };
        load_h(0); CP_COMMIT();
        load_h(1); CP_COMMIT();
        // xs prefetch for pointwise (independent of h)
#pragma unroll
        for (int q = 0; q < 2; q++) {
            int idx = tid + q * 256;
            int gate = idx >> 7, w = idx & 127, bl = w >> 2, p = w & 3;
            const float* src = g_xs + (size_t)t * 262144 + (size_t)gate * 65536
                             + (size_t)(b0 + bl) * 512 + hchunk * 16 + p * 4;
            cpa16(sb + XSB_B + ((gate * 32 + bl) * 16 + p * 4) * 4, src);
        }
        CP_COMMIT();
        load_h(2); CP_COMMIT();
        load_h(3); CP_COMMIT();

        float acc[2][4] = {};
        auto chunk = [&](int c) {
            const int kb = c * 128;
#pragma unroll
            for (int k8 = 0; k8 < 8; k8++) {
                int kk = kb + k8 * 16;
                uint32_t ahi[4], bh[4], blv[4];
                ldm_x4(ahi, sb + (HS_HI + arow + kk) * 2);
                ldm_x4(bh, sb + (brow + kk) * 2);
                ldm_x4(blv, sb + (RS_LO + brow + kk) * 2);
                mma16816(acc[0], ahi, bh[0], bh[1]);
                mma16816(acc[1], ahi, bh[2], bh[3]);
                mma16816(acc[0], ahi, blv[0], blv[1]);
                mma16816(acc[1], ahi, blv[2], blv[3]);
            }
        };
        CP_WAIT(4); __syncthreads(); chunk(0);
        CP_WAIT(3); __syncthreads(); chunk(1);
        CP_WAIT(1); __syncthreads(); chunk(2);
        CP_WAIT(0); __syncthreads(); chunk(3);

        // stage accums: accs[n][m], n = gate16 group col (0..63), m = b local, stride 33
#pragma unroll
        for (int f = 0; f < 2; f++) {
            int nl = wn + f * 8 + (lane & 3) * 2;
            int ml = wm + (lane >> 2);
            accs[nl * 33 + ml] = acc[f][0];
            accs[(nl + 1) * 33 + ml] = acc[f][1];
            accs[nl * 33 + ml + 8] = acc[f][2];
            accs[(nl + 1) * 33 + ml + 8] = acc[f][3];
        }
        __syncthreads();

        __half* hhn = g_hh[(t + 1) & 1];
#pragma unroll
        for (int s = 0; s < 2; s++) {
            int q = tid + s * 256;
            int bl = q >> 4, hl = q & 15;
            int b = b0 + bl, h = hchunk * 16 + hl;
            float ip = accs[(0 + hl) * 33 + bl]  + xsf[(0 * 32 + bl) * 16 + hl];
            float fp = accs[(16 + hl) * 33 + bl] + xsf[(1 * 32 + bl) * 16 + hl];
            float gp = accs[(32 + hl) * 33 + bl] + xsf[(2 * 32 + bl) * 16 + hl];
            float op = accs[(48 + hl) * 33 + bl] + xsf[(3 * 32 + bl) * 16 + hl];
            float ig = 1.f / (1.f + expf(-ip));
            float fg = 1.f / (1.f + expf(-fp));
            float gv = tanhf(gp);
            float og = 1.f / (1.f + expf(-op));
            float cn = gv * ig + fg * creg[s];
            creg[s] = cn;
            float hn = og * tanhf(cn);
            hlast[s] = hn;
            out[((size_t)b * 512 + t) * 512 + h] = hn;
            hhn[b * 512 + h] = __float2half_rn(hn);
        }

        // per-bchunk barrier (32 blocks share data; 4 independent groups)
        __threadfence();
        __syncthreads();
        if (tid == 0) {
            unsigned tgt = (unsigned)(t + 1) * 32u;
            atomicAdd(&g_cnt4[bchunk * 32], 1u);
            while (*(volatile unsigned*)&g_cnt4[bchunk * 32] < tgt) { __nanosleep(32); }
        }
        __syncthreads();
    }

#pragma unroll
    for (int s = 0; s < 2; s++) {
        int q = tid + s * 256;
        int bl = q >> 4, hl = q & 15;
        size_t idx = (size_t)(b0 + bl) * 512 + hchunk * 16 + hl;
        out[33554432 + idx] = hlast[s];
        out[33619968 + idx] = creg[s];
    }
}

extern "C" void kernel_launch(void* const* d_in, const int* in_sizes, int n_in,
                              void* d_out, int out_size) {
    const float* x  = (const float*)d_in[0];
    const float* h0 = (const float*)d_in[1];
    const float* c0 = (const float*)d_in[2];
    const float* We = (const float*)d_in[3];
    const float* be = (const float*)d_in[4];
    const float* Wf = (const float*)d_in[5];
    const float* bf = (const float*)d_in[6];
    const float* Wi = (const float*)d_in[7];
    const float* bi = (const float*)d_in[8];
    const float* Wg = (const float*)d_in[9];
    const float* bg = (const float*)d_in[10];
    const float* Wo = (const float*)d_in[11];
    const float* bo = (const float*)d_in[12];
    const float* Rf = (const float*)d_in[13];
    const float* Ri = (const float*)d_in[14];
    const float* Rg = (const float*)d_in[15];
    const float* Ro = (const float*)d_in[16];
    float* out = (float*)d_out;

    cudaFuncSetAttribute(xs_mm_kernel, cudaFuncAttributeMaxDynamicSharedMemorySize, XS_SMEM);
    cudaFuncSetAttribute(scan_mm_kernel, cudaFuncAttributeMaxDynamicSharedMemorySize, SC_SMEM);

    reset_kernel<<<1, 128>>>();
    wcomb_kernel<<<dim3(4, 32), 256>>>(Wi, Wf, Wg, Wo, We);
    bcomb_kernel<<<8, 256>>>(Wi, Wf, Wg, Wo, be, bi, bf, bg, bo);
    split_x_kernel<<<16384, 256>>>(x);
    split_w_kernel<<<512, 256>>>();
    split_h0_kernel<<<64, 256>>>(h0);
    split_R_kernel<<<1024, 256>>>(Ri, Rf, Rg, Ro);
    xs_mm_kernel<<<dim3(16, 512), 256, XS_SMEM>>>();
    scan_mm_kernel<<<128, 256, SC_SMEM>>>(c0, out);
}

// round 12
// speedup vs baseline: 5.9547x; 1.1832x over previous
#include <cuda_runtime.h>
#include <cuda_fp16.h>
#include <cstdint>

// B=128, T=512, DIM=256, E=512, H=512
// out = hidden_seq(33554432) + h_last at 33554432 + c_last at 33619968

__device__ __align__(16) float g_wcomb[2048 * 256];
__device__ __align__(16) float g_bcomb[2048];
__device__ __align__(16) float g_xs[134217728];      // [t][gate][b][h] fp32
__device__ __align__(16) __half g_xh[16777216];      // X fp16 [65536][256]
__device__ __align__(16) __half g_wch[524288];       // Wcomb hi [2048][256]
__device__ __align__(16) __half g_wcl[524288];       // Wcomb lo
__device__ __align__(16) __half g_rph[1048576];      // R fp16 packed [2048][512]; row=hc*64+gate*16+j <-> Rgate[hc*16+j]
__device__ __align__(16) __half g_hh[2][65536];      // h fp16 double buffer [b][k]
__device__ unsigned g_cnt4[128];                     // 4 group counters, stride 32 (128B apart)

// ---------- helpers ----------
__device__ __forceinline__ uint32_t smem_u32(const void* p) {
    uint32_t a;
    asm("{ .reg .u64 t; cvta.to.shared.u64 t, %1; cvt.u32.u64 %0, t; }" : "=r"(a) : "l"(p));
    return a;
}
__device__ __forceinline__ void ldm_x4(uint32_t* a, uint32_t addr) {
    asm volatile("ldmatrix.sync.aligned.m8n8.x4.shared.b16 {%0,%1,%2,%3}, [%4];"
                 : "=r"(a[0]), "=r"(a[1]), "=r"(a[2]), "=r"(a[3]) : "r"(addr));
}
__device__ __forceinline__ void mma16816(float* d, const uint32_t* a, uint32_t b0, uint32_t b1) {
    asm volatile("mma.sync.aligned.m16n8k16.row.col.f32.f16.f16.f32 "
                 "{%0,%1,%2,%3},{%4,%5,%6,%7},{%8,%9},{%0,%1,%2,%3};"
                 : "+f"(d[0]), "+f"(d[1]), "+f"(d[2]), "+f"(d[3])
                 : "r"(a[0]), "r"(a[1]), "r"(a[2]), "r"(a[3]), "r"(b0), "r"(b1));
}
__device__ __forceinline__ void cpa16(uint32_t saddr, const void* g) {
    asm volatile("cp.async.cg.shared.global [%0], [%1], 16;" :: "r"(saddr), "l"(g));
}
#define CP_COMMIT() asm volatile("cp.async.commit_group;" ::: "memory")
#define CP_WAIT(N)  asm volatile("cp.async.wait_group %0;" :: "n"(N) : "memory")

__device__ __forceinline__ void split1(float v, __half& h, __half& l) {
    h = __float2half_rn(v);
    l = __float2half_rn(v - __half2float(h));
}

// ---------- prep kernels ----------
__global__ void reset_kernel() {
    if (threadIdx.x < 128) g_cnt4[threadIdx.x] = 0u;
}

__global__ void wcomb_kernel(const float* __restrict__ Wi, const float* __restrict__ Wf,
                             const float* __restrict__ Wg, const float* __restrict__ Wo,
                             const float* __restrict__ We) {
    __shared__ float As[16][65];
    __shared__ float Bs[16][65];
    const int bm = blockIdx.y * 64, bn = blockIdx.x * 64, tid = threadIdx.x;
    const int tx = tid % 16, ty = tid / 16;
    float acc[4][4] = {};
    for (int k0 = 0; k0 < 512; k0 += 16) {
        for (int i = tid; i < 1024; i += 256) {
            int r = i / 16, kk = i % 16, row = bm + r, gate = row >> 9, h = row & 511;
            const float* W = (gate == 0) ? Wi : (gate == 1) ? Wf : (gate == 2) ? Wg : Wo;
            As[kk][r] = W[h * 512 + k0 + kk];
        }
        for (int i = tid; i < 1024; i += 256) {
            int kk = i / 64, c = i % 64;
            Bs[kk][c] = We[(k0 + kk) * 256 + bn + c];
        }
        __syncthreads();
#pragma unroll
        for (int kk = 0; kk < 16; kk++) {
            float a[4], b[4];
#pragma unroll
            for (int i = 0; i < 4; i++) a[i] = As[kk][ty * 4 + i];
#pragma unroll
            for (int j = 0; j < 4; j++) b[j] = Bs[kk][tx * 4 + j];
#pragma unroll
            for (int i = 0; i < 4; i++)
#pragma unroll
                for (int j = 0; j < 4; j++) acc[i][j] += a[i] * b[j];
        }
        __syncthreads();
    }
#pragma unroll
    for (int i = 0; i < 4; i++)
#pragma unroll
        for (int j = 0; j < 4; j++)
            g_wcomb[(bm + ty * 4 + i) * 256 + bn + tx * 4 + j] = acc[i][j];
}

__global__ void bcomb_kernel(const float* __restrict__ Wi, const float* __restrict__ Wf,
                             const float* __restrict__ Wg, const float* __restrict__ Wo,
                             const float* __restrict__ be,
                             const float* __restrict__ bi, const float* __restrict__ bf,
                             const float* __restrict__ bg, const float* __restrict__ bo) {
    int r = blockIdx.x * 256 + threadIdx.x;
    if (r >= 2048) return;
    int gate = r >> 9, h = r & 511;
    const float* W = (gate == 0) ? Wi : (gate == 1) ? Wf : (gate == 2) ? Wg : Wo;
    const float* bb = (gate == 0) ? bi : (gate == 1) ? bf : (gate == 2) ? bg : bo;
    float s = 0.f;
    for (int e = 0; e < 512; e++) s += W[h * 512 + e] * be[e];
    g_bcomb[r] = s + bb[h];
}

__global__ void split_x_kernel(const float* __restrict__ x) {
    size_t i = ((size_t)blockIdx.x * 256 + threadIdx.x) * 4;
    float4 v = *(const float4*)(x + i);
    ((__half2*)(g_xh + i))[0] = __floats2half2_rn(v.x, v.y);
    ((__half2*)(g_xh + i))[1] = __floats2half2_rn(v.z, v.w);
}
__global__ void split_w_kernel() {
    size_t i = ((size_t)blockIdx.x * 256 + threadIdx.x) * 4;
    float4 v = *(const float4*)(g_wcomb + i);
    __half h0, h1, h2, h3, l0, l1, l2, l3;
    split1(v.x, h0, l0); split1(v.y, h1, l1); split1(v.z, h2, l2); split1(v.w, h3, l3);
    ((__half2*)(g_wch + i))[0] = __halves2half2(h0, h1);
    ((__half2*)(g_wch + i))[1] = __halves2half2(h2, h3);
    ((__half2*)(g_wcl + i))[0] = __halves2half2(l0, l1);
    ((__half2*)(g_wcl + i))[1] = __halves2half2(l2, l3);
}
__global__ void split_h0_kernel(const float* __restrict__ h0) {
    size_t i = ((size_t)blockIdx.x * 256 + threadIdx.x) * 4;
    float4 v = *(const float4*)(h0 + i);
    ((__half2*)(g_hh[0] + i))[0] = __floats2half2_rn(v.x, v.y);
    ((__half2*)(g_hh[0] + i))[1] = __floats2half2_rn(v.z, v.w);
}
__global__ void split_R_kernel(const float* __restrict__ Ri, const float* __restrict__ Rf,
                               const float* __restrict__ Rg, const float* __restrict__ Ro) {
    size_t i = (size_t)blockIdx.x * 256 + threadIdx.x;   // 262144 quads
    int r = (int)(i >> 7), k = (int)(i & 127) * 4;
    int hc = r >> 6, w = r & 63, gate = w >> 4, j = w & 15;
    int h = hc * 16 + j;
    const float* R = (gate == 0) ? Ri : (gate == 1) ? Rf : (gate == 2) ? Rg : Ro;
    float4 v = *(const float4*)(R + (size_t)h * 512 + k);
    ((__half2*)(g_rph + (size_t)r * 512 + k))[0] = __floats2half2_rn(v.x, v.y);
    ((__half2*)(g_rph + (size_t)r * 512 + k))[1] = __floats2half2_rn(v.z, v.w);
}

// ---------- xs GEMM: X fp16 x W split-fp16 (2 terms) ----------
// C[65536,2048] = X @ Wcomb^T + bcomb. grid(16,512): bn=blockIdx.x*128, bm=blockIdx.y*128.
// per buf (halves): A @0, Bh @9216, Bl @18432; buf stride 27648. stride 72/row.
#define XS_SMEM 110592
__global__ void __launch_bounds__(256) xs_mm_kernel() {
    extern __shared__ __half xsm[];
    uint32_t sb = smem_u32(xsm);
    const int tid = threadIdx.x, lane = tid & 31, wid = tid >> 5;
    const int bn = blockIdx.x * 128, bm = blockIdx.y * 128;
    const int wm = (wid & 1) * 64, wn = (wid >> 1) * 32;

    float acc[4][4][4] = {};

    auto load_kc = [&](int kc) {
        uint32_t base = (kc & 1) * 27648;
        const int kcol = kc * 64;
#pragma unroll
        for (int q = 0; q < 4; q++) {
            int idx = tid + q * 256, r = idx >> 3, u = idx & 7;
            size_t ga = (size_t)(bm + r) * 256 + kcol + u * 8;
            size_t gb = (size_t)(bn + r) * 256 + kcol + u * 8;
            uint32_t so = (base + r * 72 + u * 8) * 2;
            cpa16(sb + so, g_xh + ga);
            cpa16(sb + so + 18432, g_wch + gb);
            cpa16(sb + so + 36864, g_wcl + gb);
        }
    };

    load_kc(0);
    CP_COMMIT();
    for (int kc = 0; kc < 4; kc++) {
        if (kc < 3) { load_kc(kc + 1); CP_COMMIT(); CP_WAIT(1); }
        else        { CP_WAIT(0); }
        __syncthreads();
        const uint32_t ah = sb + ((kc & 1) * 27648) * 2;
        const uint32_t bhb = ah + 18432, blb = ah + 36864;
        const uint32_t aoff = (wm + (lane & 15)) * 72 + ((lane >> 4) << 3);
        const uint32_t boff0 = (wn + ((lane >> 4) << 3) + (lane & 7)) * 72 + (((lane >> 3) & 1) << 3);
        const uint32_t boff1 = boff0 + 16 * 72;
#pragma unroll
        for (int kk = 0; kk < 64; kk += 16) {
            uint32_t bh01[4], bh23[4], bl01[4], bl23[4];
            ldm_x4(bh01, bhb + (boff0 + kk) * 2);
            ldm_x4(bh23, bhb + (boff1 + kk) * 2);
            ldm_x4(bl01, blb + (boff0 + kk) * 2);
            ldm_x4(bl23, blb + (boff1 + kk) * 2);
#pragma unroll
            for (int i = 0; i < 4; i++) {
                uint32_t ahi[4];
                ldm_x4(ahi, ah + (aoff + i * 16 * 72 + kk) * 2);
                mma16816(acc[i][0], ahi, bh01[0], bh01[1]);
                mma16816(acc[i][1], ahi, bh01[2], bh01[3]);
                mma16816(acc[i][2], ahi, bh23[0], bh23[1]);
                mma16816(acc[i][3], ahi, bh23[2], bh23[3]);
                mma16816(acc[i][0], ahi, bl01[0], bl01[1]);
                mma16816(acc[i][1], ahi, bl01[2], bl01[3]);
                mma16816(acc[i][2], ahi, bl23[0], bl23[1]);
                mma16816(acc[i][3], ahi, bl23[2], bl23[3]);
            }
        }
        __syncthreads();
    }

    const int gate = bn >> 9, hb = bn & 511;
#pragma unroll
    for (int f = 0; f < 4; f++) {
        int nl = wn + f * 8 + (lane & 3) * 2;
        float b0v = g_bcomb[bn + nl], b1v = g_bcomb[bn + nl + 1];
#pragma unroll
        for (int i = 0; i < 4; i++) {
            int m0 = bm + wm + i * 16 + (lane >> 2);
#pragma unroll
            for (int rr = 0; rr < 2; rr++) {
                int m = m0 + rr * 8;
                int t = m & 511, b = m >> 9;
                float2 v = make_float2(acc[i][f][rr * 2 + 0] + b0v, acc[i][f][rr * 2 + 1] + b1v);
                *(float2*)(g_xs + (((size_t)t * 4 + gate) * 128 + b) * 512 + hb + nl) = v;
            }
        }
    }
}

// ---------- persistent scan: h fp16 x R fp16 (1 term) ----------
// 128 blocks x 256 thr. Block=(bchunk: 32 batches, hchunk: 16 h x 4 gates = N64).
// smem halves: R @0 (64x520), h @33280 (32x520).
// bytes: accs @99840 (64x33 f32), xsbuf @108288 (128x16 f32). total 116480.
#define HS_OFF 33280
#define ACC_B 99840
#define XSB_B 108288
#define SC_SMEM 116480
__global__ void __launch_bounds__(256, 1) scan_mm_kernel(const float* __restrict__ c0,
                                                         float* __restrict__ out) {
    extern __shared__ __half ssm[];
    uint32_t sb = smem_u32(ssm);
    float* accs = (float*)((char*)ssm + ACC_B);
    float* xsf = (float*)((char*)ssm + XSB_B);
    const int tid = threadIdx.x, lane = tid & 31, wid = tid >> 5;
    const int bchunk = blockIdx.x >> 5, hchunk = blockIdx.x & 31;
    const int b0 = bchunk * 32;
    const int wm = (wid & 1) * 16, wn = (wid >> 1) * 16;

    // R resident (fp16)
#pragma unroll
    for (int q = 0; q < 16; q++) {
        int idx = tid + q * 256;
        int r = idx >> 6, u = idx & 63;
        const __half* src = g_rph + (size_t)(hchunk * 64 + r) * 512 + u * 8;
        *(uint4*)((char*)ssm + (r * 520 + u * 8) * 2) = *(const uint4*)src;
    }
    __syncthreads();

    float creg[2], hlast[2];
#pragma unroll
    for (int s = 0; s < 2; s++) {
        int q = tid + s * 256;
        int bl = q >> 4, hl = q & 15;
        creg[s] = c0[(b0 + bl) * 512 + hchunk * 16 + hl];
        hlast[s] = 0.f;
    }

    const uint32_t arow = (wm + (lane & 15)) * 520 + ((lane >> 4) << 3);
    const uint32_t brow = (wn + ((lane >> 4) << 3) + (lane & 7)) * 520 + (((lane >> 3) & 1) << 3);

    for (int t = 0; t < 512; t++) {
        const __half* hhp = g_hh[t & 1];

        auto load_h = [&](int c) {
#pragma unroll
            for (int q = 0; q < 2; q++) {
                int idx = tid + q * 256;
                int r = idx >> 4, u = idx & 15;
                const __half* src = hhp + (size_t)(b0 + r) * 512 + c * 128 + u * 8;
                cpa16(sb + (HS_OFF + r * 520 + c * 128 + u * 8) * 2, src);
            }
        };
        load_h(0); CP_COMMIT();
        load_h(1); CP_COMMIT();
        // xs prefetch for pointwise (independent of h)
#pragma unroll
        for (int q = 0; q < 2; q++) {
            int idx = tid + q * 256;
            int gate = idx >> 7, w = idx & 127, bl = w >> 2, p = w & 3;
            const float* src = g_xs + (size_t)t * 262144 + (size_t)gate * 65536
                             + (size_t)(b0 + bl) * 512 + hchunk * 16 + p * 4;
            cpa16(sb + XSB_B + ((gate * 32 + bl) * 16 + p * 4) * 4, src);
        }
        CP_COMMIT();
        load_h(2); CP_COMMIT();
        load_h(3); CP_COMMIT();

        float acc[2][4] = {};
        auto chunk = [&](int c) {
            const int kb = c * 128;
#pragma unroll
            for (int k8 = 0; k8 < 8; k8++) {
                int kk = kb + k8 * 16;
                uint32_t ahi[4], bh[4];
                ldm_x4(ahi, sb + (HS_OFF + arow + kk) * 2);
                ldm_x4(bh, sb + (brow + kk) * 2);
                mma16816(acc[0], ahi, bh[0], bh[1]);
                mma16816(acc[1], ahi, bh[2], bh[3]);
            }
        };
        CP_WAIT(4); __syncthreads(); chunk(0);
        CP_WAIT(3); __syncthreads(); chunk(1);
        CP_WAIT(1); __syncthreads(); chunk(2);
        CP_WAIT(0); __syncthreads(); chunk(3);

        // stage accums: accs[n][m], n = gate16 group col (0..63), m = b local, stride 33
#pragma unroll
        for (int f = 0; f < 2; f++) {
            int nl = wn + f * 8 + (lane & 3) * 2;
            int ml = wm + (lane >> 2);
            accs[nl * 33 + ml] = acc[f][0];
            accs[(nl + 1) * 33 + ml] = acc[f][1];
            accs[nl * 33 + ml + 8] = acc[f][2];
            accs[(nl + 1) * 33 + ml + 8] = acc[f][3];
        }
        __syncthreads();

        __half* hhn = g_hh[(t + 1) & 1];
#pragma unroll
        for (int s = 0; s < 2; s++) {
            int q = tid + s * 256;
            int bl = q >> 4, hl = q & 15;
            int b = b0 + bl, h = hchunk * 16 + hl;
            float ip = accs[(0 + hl) * 33 + bl]  + xsf[(0 * 32 + bl) * 16 + hl];
            float fp = accs[(16 + hl) * 33 + bl] + xsf[(1 * 32 + bl) * 16 + hl];
            float gp = accs[(32 + hl) * 33 + bl] + xsf[(2 * 32 + bl) * 16 + hl];
            float op = accs[(48 + hl) * 33 + bl] + xsf[(3 * 32 + bl) * 16 + hl];
            float ig = 1.f / (1.f + expf(-ip));
            float fg = 1.f / (1.f + expf(-fp));
            float gv = tanhf(gp);
            float og = 1.f / (1.f + expf(-op));
            float cn = gv * ig + fg * creg[s];
            creg[s] = cn;
            float hn = og * tanhf(cn);
            hlast[s] = hn;
            out[((size_t)b * 512 + t) * 512 + h] = hn;
            hhn[b * 512 + h] = __float2half_rn(hn);
        }

        // per-bchunk barrier (32 blocks share data; 4 independent groups)
        __threadfence();
        __syncthreads();
        if (tid == 0) {
            unsigned tgt = (unsigned)(t + 1) * 32u;
            atomicAdd(&g_cnt4[bchunk * 32], 1u);
            while (*(volatile unsigned*)&g_cnt4[bchunk * 32] < tgt) { __nanosleep(32); }
        }
        __syncthreads();
    }

#pragma unroll
    for (int s = 0; s < 2; s++) {
        int q = tid + s * 256;
        int bl = q >> 4, hl = q & 15;
        size_t idx = (size_t)(b0 + bl) * 512 + hchunk * 16 + hl;
        out[33554432 + idx] = hlast[s];
        out[33619968 + idx] = creg[s];
    }
}

extern "C" void kernel_launch(void* const* d_in, const int* in_sizes, int n_in,
                              void* d_out, int out_size) {
    const float* x  = (const float*)d_in[0];
    const float* h0 = (const float*)d_in[1];
    const float* c0 = (const float*)d_in[2];
    const float* We = (const float*)d_in[3];
    const float* be = (const float*)d_in[4];
    const float* Wf = (const float*)d_in[5];
    const float* bf = (const float*)d_in[6];
    const float* Wi = (const float*)d_in[7];
    const float* bi = (const float*)d_in[8];
    const float* Wg = (const float*)d_in[9];
    const float* bg = (const float*)d_in[10];
    const float* Wo = (const float*)d_in[11];
    const float* bo = (const float*)d_in[12];
    const float* Rf = (const float*)d_in[13];
    const float* Ri = (const float*)d_in[14];
    const float* Rg = (const float*)d_in[15];
    const float* Ro = (const float*)d_in[16];
    float* out = (float*)d_out;

    cudaFuncSetAttribute(xs_mm_kernel, cudaFuncAttributeMaxDynamicSharedMemorySize, XS_SMEM);
    cudaFuncSetAttribute(scan_mm_kernel, cudaFuncAttributeMaxDynamicSharedMemorySize, SC_SMEM);

    reset_kernel<<<1, 128>>>();
    wcomb_kernel<<<dim3(4, 32), 256>>>(Wi, Wf, Wg, Wo, We);
    bcomb_kernel<<<8, 256>>>(Wi, Wf, Wg, Wo, be, bi, bf, bg, bo);
    split_x_kernel<<<16384, 256>>>(x);
    split_w_kernel<<<512, 256>>>();
    split_h0_kernel<<<64, 256>>>(h0);
    split_R_kernel<<<1024, 256>>>(Ri, Rf, Rg, Ro);
    xs_mm_kernel<<<dim3(16, 512), 256, XS_SMEM>>>();
    scan_mm_kernel<<<128, 256, SC_SMEM>>>(c0, out);
}